// round 15
// baseline (speedup 1.0000x reference)
#include <cuda_runtime.h>
#include <cuda_bf16.h>
#include <cuda_fp16.h>
#include <cstdint>

#define BB     8
#define HH     64
#define WW     64
#define NPIX   32768
#define DIM    192
#define QKVN   576
#define HEADSB 2
#define HEADD  32
#define KEXT   384        // hi(192) | lo(192) bf16

typedef unsigned long long u64;
typedef unsigned int u32;

// Scratch (device globals: allocation-free rule)
__device__ float         g_q[(size_t)NPIX * DIM];          // pre-scaled q, [pix][192]
__device__ __half        g_k[(size_t)3 * NPIX * 64];       // [branch][pix][64] fp16
__device__ __half        g_v[(size_t)3 * NPIX * 64];       // [branch][pix][64] fp16
__device__ __nv_bfloat16 g_xe[(size_t)NPIX * KEXT];
__device__ __nv_bfloat16 g_ye[(size_t)NPIX * KEXT];
__device__ __nv_bfloat16 g_wqe[(size_t)QKVN * KEXT];
__device__ __nv_bfloat16 g_wpe[(size_t)DIM * KEXT];

// ---- f32x2 helpers ---------------------------------------------------------
__device__ __forceinline__ void ffma2(u64& d, u64 a, u64 b) {
    asm("fma.rn.f32x2 %0, %1, %2, %0;" : "+l"(d) : "l"(a), "l"(b));
}
__device__ __forceinline__ u64 dup2(float v) {
    u64 r; asm("mov.b64 %0, {%1, %1};" : "=l"(r) : "f"(v)); return r;
}
__device__ __forceinline__ u64 pk2(float lo, float hi) {
    u64 r; asm("mov.b64 %0, {%1, %2};" : "=l"(r) : "f"(lo), "f"(hi)); return r;
}
__device__ __forceinline__ void unpk2(u64 v, float& lo, float& hi) {
    asm("mov.b64 {%0, %1}, %2;" : "=f"(lo), "=f"(hi) : "l"(v));
}
__device__ __forceinline__ u32 sToU32(const void* p) {
    u32 a;
    asm("{ .reg .u64 t; cvta.to.shared.u64 t, %1; cvt.u32.u64 %0, t; }" : "=r"(a) : "l"(p));
    return a;
}

// ---- warp MMA primitives ----------------------------------------------------
#define LDSM4(r, addr) \
    asm volatile("ldmatrix.sync.aligned.m8n8.x4.shared.b16 {%0,%1,%2,%3}, [%4];" \
                 : "=r"((r)[0]), "=r"((r)[1]), "=r"((r)[2]), "=r"((r)[3]) : "r"(addr))

__device__ __forceinline__ void hmma(float* c, const u32* a, u32 b0, u32 b1) {
    asm volatile(
        "mma.sync.aligned.m16n8k16.row.col.f32.bf16.bf16.f32 "
        "{%0,%1,%2,%3}, {%4,%5,%6,%7}, {%8,%9}, {%0,%1,%2,%3};"
        : "+f"(c[0]), "+f"(c[1]), "+f"(c[2]), "+f"(c[3])
        : "r"(a[0]), "r"(a[1]), "r"(a[2]), "r"(a[3]), "r"(b0), "r"(b1));
}

#define CPA16(s, g)  asm volatile("cp.async.cg.shared.global [%0], [%1], 16;" :: "r"(s), "l"(g))
#define CPA_COMMIT() asm volatile("cp.async.commit_group;" ::: "memory")
#define CPA_WAITN(n) asm volatile("cp.async.wait_group %0;" :: "n"(n) : "memory")

// ---------------------------------------------------------------------------
// conv_all: merged conv_x (blocks 0..6143) + conv_w (blocks 6144..6719)
// ---------------------------------------------------------------------------
__global__ __launch_bounds__(256) void conv_all(const float* __restrict__ x,
                                                const float* __restrict__ wq,
                                                const float* __restrict__ wp) {
    const int bb = blockIdx.x;
    if (bb < 6144) {
        __shared__ float t[32][33];
        const int tx = threadIdx.x & 31, ty = threadIdx.x >> 5;
        const int s0 = (bb & 127) * 32;
        const int k0 = ((bb >> 7) % 6) * 32;
        const int b  = bb / 768;
        const float* xb = x + ((size_t)b * DIM + k0) * 4096 + s0;
        #pragma unroll
        for (int r = 0; r < 4; r++)
            t[ty + 8 * r][tx] = xb[(size_t)(ty + 8 * r) * 4096 + tx];
        __syncthreads();
        #pragma unroll
        for (int r = 0; r < 4; r++) {
            const int sl = ty + 8 * r;
            const float v = t[tx][sl];
            const __nv_bfloat16 h = __float2bfloat16(v);
            const __nv_bfloat16 l = __float2bfloat16(v - __bfloat162float(h));
            __nv_bfloat16* row = g_xe + (size_t)((b << 12) + s0 + sl) * KEXT;
            row[k0 + tx]       = h;
            row[192 + k0 + tx] = l;
        }
    } else {
        int i = (bb - 6144) * 256 + threadIdx.x;
        if (i < QKVN * DIM) {
            const int n = i / DIM, k = i % DIM;
            const float v = wq[i];
            const __nv_bfloat16 h = __float2bfloat16(v);
            const __nv_bfloat16 l = __float2bfloat16(v - __bfloat162float(h));
            g_wqe[(size_t)n * KEXT + k] = h;
            g_wqe[(size_t)n * KEXT + 192 + k] = l;
        } else {
            i -= QKVN * DIM;
            if (i < DIM * DIM) {
                const int n = i / DIM, k = i % DIM;
                const float v = wp[i];
                const __nv_bfloat16 h = __float2bfloat16(v);
                const __nv_bfloat16 l = __float2bfloat16(v - __bfloat162float(h));
                g_wpe[(size_t)n * KEXT + k] = h;
                g_wpe[(size_t)n * KEXT + 192 + k] = l;
            }
        }
    }
}

// ---------------------------------------------------------------------------
// HMMA GEMM, CTA MTILE x 64, 8 warps (4m x 2n), extended-K split.
// B resident (48 KB); A streamed in 6 octs via 4-slot ring.
// EPI=0 (MTILE=128): routed q/k/v stores.  EPI=1 (MTILE=64): CHW out.
// ---------------------------------------------------------------------------
#define NT 64
#define SM_B 0                      // B: 64 rows x 768 B = 49152
#define SM_A 49152

template<int EPI, int MTILE>
__global__ __launch_bounds__(256, 2) void hmma_gemm(const __nv_bfloat16* __restrict__ A,
                                                    const __nv_bfloat16* __restrict__ Bw,
                                                    const float* __restrict__ bias,
                                                    float* __restrict__ outp) {
    constexpr int MW = MTILE / 64;          // 16-row subtiles per warp
    constexpr int OCT = MTILE * 128;        // bytes per A oct
    extern __shared__ char smem[];
    const u32 sb = sToU32(smem);
    const int tid = threadIdx.x;
    const int wid = tid >> 5, lane = tid & 31;
    const int m0 = blockIdx.x * MTILE;
    const int n0 = blockIdx.y * NT;

    const __nv_bfloat16* Ab = A + (size_t)m0 * KEXT;
    const __nv_bfloat16* Bb = Bw + (size_t)n0 * KEXT;

    // ---- prologue: B (48 KB, group0) then A octs 0..3 (groups 1-4)
    #pragma unroll
    for (int i = 0; i < 12; i++) {                       // B: 64 rows x 48 chunks
        const int idx = tid + i * 256;
        const int r = idx / 48, c = idx % 48;
        CPA16(sb + SM_B + r * 768 + ((c ^ (r & 7)) << 4), Bb + (size_t)r * KEXT + c * 8);
    }
    CPA_COMMIT();
    #pragma unroll
    for (int o = 0; o < 4; o++) {                        // A octs: MTILE rows x 8 chunks
        #pragma unroll
        for (int i = 0; i < MTILE / 32; i++) {
            const int idx = tid + i * 256;
            const int r = idx >> 3, c = idx & 7;
            CPA16(sb + SM_A + o * OCT + r * 128 + ((c ^ (r & 7)) << 4),
                  Ab + (size_t)r * KEXT + (o * 8 + c) * 8);
        }
        CPA_COMMIT();
    }

    const int warpM = (wid >> 1) * (MTILE / 4);
    const int warpN = (wid & 1) * 32;
    const int lr = lane & 15;
    const int lh = lane >> 4;
    const int asw = lr & 7;
    u32 bBase[2]; int bsw[2];
    #pragma unroll
    for (int g = 0; g < 2; g++) {
        const int row = warpN + g * 16 + lr;
        bBase[g] = sb + SM_B + row * 768;
        bsw[g]   = row & 7;
    }

    float acc[MW][4][4] = {};

    #pragma unroll
    for (int st = 0; st < 6; st++) {
        if (st < 3) { CPA_WAITN(3); }
        else if (st == 3) { CPA_WAITN(2); }
        else if (st == 4) { CPA_WAITN(1); }
        else { CPA_WAITN(0); }
        __syncthreads();

        const int slot = st & 3;
        const u32 aB = sb + SM_A + slot * OCT + (warpM + lr) * 128;
        const int nk = (st < 3) ? 8 : 4;
        #pragma unroll
        for (int kk = 0; kk < 8; kk++) {
            if (kk >= nk) break;
            const int boct = (st < 3) ? ((kk < 4) ? st : st + 3) : (st - 3);
            const int al = kk & 3;
            u32 af[MW][4];
            #pragma unroll
            for (int mw = 0; mw < MW; mw++)
                LDSM4(af[mw], aB + mw * 16 * 128 + (((al * 2 + lh) ^ asw) << 4));
            const int bc = boct * 8 + al * 2 + lh;
            u32 bf[2][4];
            #pragma unroll
            for (int g = 0; g < 2; g++)
                LDSM4(bf[g], bBase[g] + ((bc ^ bsw[g]) << 4));
            #pragma unroll
            for (int mw = 0; mw < MW; mw++)
                #pragma unroll
                for (int j = 0; j < 4; j++) {
                    const int g = j >> 1, p = j & 1;
                    hmma(acc[mw][j], af[mw], bf[g][p], bf[g][p + 2]);
                }
        }
        __syncthreads();
        if (st < 2) {
            #pragma unroll
            for (int i = 0; i < MTILE / 32; i++) {
                const int idx = tid + i * 256;
                const int r = idx >> 3, c = idx & 7;
                CPA16(sb + SM_A + slot * OCT + r * 128 + ((c ^ (r & 7)) << 4),
                      Ab + (size_t)r * KEXT + ((st + 4) * 8 + c) * 8);
            }
            CPA_COMMIT();
        }
    }

    // ---- epilogue (smem reuse)
    if (EPI == 0) {
        float* Ct = (float*)smem;   // [MTILE][68]
        #pragma unroll
        for (int mw = 0; mw < MW; mw++) {
            #pragma unroll
            for (int j = 0; j < 4; j++) {
                const int rm = warpM + mw * 16 + (lane >> 2);
                const int rn = warpN + j * 8 + (lane & 3) * 2;
                Ct[rm * 68 + rn]           = acc[mw][j][0];
                Ct[rm * 68 + rn + 1]       = acc[mw][j][1];
                Ct[(rm + 8) * 68 + rn]     = acc[mw][j][2];
                Ct[(rm + 8) * 68 + rn + 1] = acc[mw][j][3];
            }
        }
        __syncthreads();
        const int br = n0 / 192, rr = n0 % 192, sec = rr >> 6;
        #pragma unroll
        for (int i = 0; i < MTILE / 16; i++) {
            const int idx = tid + i * 256;
            const int m = idx >> 4, c = (idx & 15) * 4;
            const float4 bv = *(const float4*)&bias[n0 + c];
            float4 v;
            v.x = Ct[m * 68 + c]     + bv.x;
            v.y = Ct[m * 68 + c + 1] + bv.y;
            v.z = Ct[m * 68 + c + 2] + bv.z;
            v.w = Ct[m * 68 + c + 3] + bv.w;
            const size_t pix = m0 + m;
            if (sec == 0) {
                const float qsc = 0.17677669529663687f;
                v.x *= qsc; v.y *= qsc; v.z *= qsc; v.w *= qsc;
                *(float4*)&g_q[pix * DIM + br * 64 + c] = v;
            } else {
                __half2 h0 = __float22half2_rn(make_float2(v.x, v.y));
                __half2 h1 = __float22half2_rn(make_float2(v.z, v.w));
                __half* dst = (sec == 1) ? g_k : g_v;
                __half2* vp = (__half2*)&dst[((size_t)(br << 15) + pix) * 64 + c];
                vp[0] = h0; vp[1] = h1;
            }
        }
    } else {
        float* Ct = (float*)smem;   // [64][MTILE+4] transposed
        #pragma unroll
        for (int mw = 0; mw < MW; mw++) {
            #pragma unroll
            for (int j = 0; j < 4; j++) {
                const int rn = warpN + j * 8 + (lane & 3) * 2;
                const int rm = warpM + mw * 16 + (lane >> 2);
                Ct[rn * (MTILE + 4) + rm]           = acc[mw][j][0];
                Ct[(rn + 1) * (MTILE + 4) + rm]     = acc[mw][j][1];
                Ct[rn * (MTILE + 4) + rm + 8]       = acc[mw][j][2];
                Ct[(rn + 1) * (MTILE + 4) + rm + 8] = acc[mw][j][3];
            }
        }
        __syncthreads();
        const int b = m0 >> 12, s0 = m0 & 4095;
        float* ob = outp + ((size_t)b * DIM + n0) * 4096 + s0;
        #pragma unroll
        for (int i = 0; i < NT * MTILE / 256; i++) {
            const int idx = tid + i * 256;
            const int n = idx / MTILE, m = idx % MTILE;
            ob[(size_t)n * 4096 + m] = Ct[n * (MTILE + 4) + m] + bias[n0 + n];
        }
    }
}

// ---------------------------------------------------------------------------
// NATTEN: 8 lanes per (pixel, head); k,v fp16 (fp32 math); rpb in smem;
// k+v rows loaded together; max-free softmax. Output split bf16 into g_ye.
// ---------------------------------------------------------------------------
template<int K, int D, int BR>
__device__ __forceinline__ void natten_body(const float* __restrict__ rpb, int blk,
                                            float* __restrict__ srpb) {
    for (int i = threadIdx.x; i < 2 * (2 * K - 1) * (2 * K - 1); i += 256)
        srpb[i] = rpb[i];
    __syncthreads();

    const int sl   = threadIdx.x & 7;
    const int gid  = (blk * 256 + threadIdx.x) >> 3;
    const int head = gid & 1;
    const int pix  = gid >> 1;
    const int w = pix & 63;
    const int h = (pix >> 6) & 63;
    const int b = pix >> 12;

    const float4 q = *(const float4*)&g_q[(size_t)pix * DIM + BR * 64 + head * HEADD + sl * 4];

    const int gh = h % D, iih = h / D;
    const int Lgh = (HH - gh + D - 1) / D;
    const int sth = min(max(iih - K / 2, 0), Lgh - K);
    const int gw = w % D, iiw = w / D;
    const int Lgw = (WW - gw + D - 1) / D;
    const int stw = min(max(iiw - K / 2, 0), Lgw - K);

    const float* rpbh = srpb + head * (2 * K - 1) * (2 * K - 1)
                       + (sth - iih + K - 1) * (2 * K - 1)
                       + (stw - iiw + K - 1);

    const size_t nb0 = (size_t)(BR << 15) + (b << 12) + (gh + sth * D) * 64 + (gw + stw * D);
    const __half* kbase = g_k + nb0 * 64 + head * HEADD + sl * 4;
    const __half* vbase = g_v + nb0 * 64 + head * HEADD + sl * 4;

    const int strideWk = D * 64;
    const int strideHk = D * 64 * 64;

    float l = 0.f;
    u64 acc0 = 0, acc1 = 0;

    #pragma unroll
    for (int kh = 0; kh < K; kh++) {
        const __half* pk = kbase + (size_t)kh * strideHk;
        const __half* pv = vbase + (size_t)kh * strideHk;
        float sarr[K];
        u64 varr[K];
        #pragma unroll
        for (int kw = 0; kw < K; kw++) {
            const u64 k4p = *(const u64*)(pk + (size_t)kw * strideWk);
            varr[kw] = *(const u64*)(pv + (size_t)kw * strideWk);
            const __half2* kh2 = (const __half2*)&k4p;
            const float2 k01 = __half22float2(kh2[0]);
            const float2 k23 = __half22float2(kh2[1]);
            sarr[kw] = q.x * k01.x + q.y * k01.y + q.z * k23.x + q.w * k23.y;
        }
        #pragma unroll
        for (int kw = 0; kw < K; kw++) {
            float s = sarr[kw];
            s += __shfl_xor_sync(0xffffffffu, s, 4);
            s += __shfl_xor_sync(0xffffffffu, s, 2);
            s += __shfl_xor_sync(0xffffffffu, s, 1);
            sarr[kw] = __expf(s + rpbh[kh * (2 * K - 1) + kw]);
        }
        #pragma unroll
        for (int kw = 0; kw < K; kw++) {
            const float pr = sarr[kw];
            l += pr;
            const u64 prd = dup2(pr);
            const __half2* vh = (const __half2*)&varr[kw];
            const float2 f01 = __half22float2(vh[0]);
            const float2 f23 = __half22float2(vh[1]);
            ffma2(acc0, pk2(f01.x, f01.y), prd);
            ffma2(acc1, pk2(f23.x, f23.y), prd);
        }
    }
    const float rinv = __frcp_rn(l);
    float o[4];
    unpk2(acc0, o[0], o[1]);
    unpk2(acc1, o[2], o[3]);

    const int c = BR * 64 + head * HEADD + sl * 4;
    __nv_bfloat16 hi[4], lo[4];
    #pragma unroll
    for (int i = 0; i < 4; i++) {
        const float v = o[i] * rinv;
        hi[i] = __float2bfloat16(v);
        lo[i] = __float2bfloat16(v - __bfloat162float(hi[i]));
    }
    __nv_bfloat16* yr = g_ye + (size_t)pix * KEXT;
    *(u64*)(yr + c)       = *(const u64*)hi;
    *(u64*)(yr + 192 + c) = *(const u64*)lo;
}

#define ABLOCKS (NPIX * HEADSB / 32)   // 2048 blocks per branch

__global__ __launch_bounds__(256) void natten_all(const float* __restrict__ rpb0,
                                                  const float* __restrict__ rpb1,
                                                  const float* __restrict__ rpb2) {
    __shared__ float srpb[338];
    const int br  = blockIdx.x % 3;
    const int idx = blockIdx.x / 3;
    if (br == 0)      natten_body<3, 1, 0>(rpb0, idx, srpb);
    else if (br == 1) natten_body<5, 2, 1>(rpb1, idx, srpb);
    else              natten_body<7, 3, 2>(rpb2, idx, srpb);
}

// ---------------------------------------------------------------------------
extern "C" void kernel_launch(void* const* d_in, const int* in_sizes, int n_in,
                              void* d_out, int out_size) {
    const float* x      = (const float*)d_in[0];
    const float* qkv_w  = (const float*)d_in[1];
    const float* qkv_b  = (const float*)d_in[2];
    const float* proj_w = (const float*)d_in[3];
    const float* proj_b = (const float*)d_in[4];
    const float* rpb0   = (const float*)d_in[5];
    const float* rpb1   = (const float*)d_in[6];
    const float* rpb2   = (const float*)d_in[7];
    float* out = (float*)d_out;

    static bool init_done = false;
    if (!init_done) {
        cudaFuncSetAttribute((const void*)hmma_gemm<0, 128>,
                             cudaFuncAttributeMaxDynamicSharedMemorySize, 49152 + 4 * 128 * 128);
        cudaFuncSetAttribute((const void*)hmma_gemm<1, 64>,
                             cudaFuncAttributeMaxDynamicSharedMemorySize, 49152 + 4 * 64 * 128);
        init_done = true;
    }

    __nv_bfloat16* xe  = nullptr; cudaGetSymbolAddress((void**)&xe,  g_xe);
    __nv_bfloat16* ye  = nullptr; cudaGetSymbolAddress((void**)&ye,  g_ye);
    __nv_bfloat16* wqe = nullptr; cudaGetSymbolAddress((void**)&wqe, g_wqe);
    __nv_bfloat16* wpe = nullptr; cudaGetSymbolAddress((void**)&wpe, g_wpe);

    conv_all<<<6720, 256>>>(x, qkv_w, proj_w);

    hmma_gemm<0, 128><<<dim3(NPIX / 128, QKVN / NT), 256, 49152 + 4 * 128 * 128>>>(xe, wqe, qkv_b, nullptr);

    natten_all<<<3 * ABLOCKS, 256>>>(rpb0, rpb1, rpb2);

    hmma_gemm<1, 64><<<dim3(NPIX / 64, DIM / NT), 256, 49152 + 4 * 64 * 128>>>(ye, wpe, proj_b, out);
}

// round 16
// speedup vs baseline: 1.0153x; 1.0153x over previous
#include <cuda_runtime.h>
#include <cuda_bf16.h>
#include <cuda_fp16.h>
#include <cstdint>

#define BB     8
#define HH     64
#define WW     64
#define NPIX   32768
#define DIM    192
#define QKVN   576
#define HEADSB 2
#define HEADD  32
#define KEXT   384        // hi(192) | lo(192) bf16

typedef unsigned long long u64;
typedef unsigned int u32;

// Scratch (device globals: allocation-free rule)
__device__ float         g_q[(size_t)NPIX * DIM];          // pre-scaled q, [pix][192]
__device__ __half        g_k[(size_t)3 * NPIX * 64];       // [branch][pix][64] fp16
__device__ __half        g_v[(size_t)3 * NPIX * 64];       // [branch][pix][64] fp16
__device__ __nv_bfloat16 g_xe[(size_t)NPIX * KEXT];
__device__ __nv_bfloat16 g_ye[(size_t)NPIX * KEXT];
__device__ __nv_bfloat16 g_wqe[(size_t)QKVN * KEXT];
__device__ __nv_bfloat16 g_wpe[(size_t)DIM * KEXT];

// ---- f32x2 helpers ---------------------------------------------------------
__device__ __forceinline__ void ffma2(u64& d, u64 a, u64 b) {
    asm("fma.rn.f32x2 %0, %1, %2, %0;" : "+l"(d) : "l"(a), "l"(b));
}
__device__ __forceinline__ u64 dup2(float v) {
    u64 r; asm("mov.b64 %0, {%1, %1};" : "=l"(r) : "f"(v)); return r;
}
__device__ __forceinline__ u64 pk2(float lo, float hi) {
    u64 r; asm("mov.b64 %0, {%1, %2};" : "=l"(r) : "f"(lo), "f"(hi)); return r;
}
__device__ __forceinline__ void unpk2(u64 v, float& lo, float& hi) {
    asm("mov.b64 {%0, %1}, %2;" : "=f"(lo), "=f"(hi) : "l"(v));
}
__device__ __forceinline__ u32 sToU32(const void* p) {
    u32 a;
    asm("{ .reg .u64 t; cvta.to.shared.u64 t, %1; cvt.u32.u64 %0, t; }" : "=r"(a) : "l"(p));
    return a;
}

// ---- warp MMA primitives ----------------------------------------------------
#define LDSM4(r, addr) \
    asm volatile("ldmatrix.sync.aligned.m8n8.x4.shared.b16 {%0,%1,%2,%3}, [%4];" \
                 : "=r"((r)[0]), "=r"((r)[1]), "=r"((r)[2]), "=r"((r)[3]) : "r"(addr))

__device__ __forceinline__ void hmma(float* c, const u32* a, u32 b0, u32 b1) {
    asm volatile(
        "mma.sync.aligned.m16n8k16.row.col.f32.bf16.bf16.f32 "
        "{%0,%1,%2,%3}, {%4,%5,%6,%7}, {%8,%9}, {%0,%1,%2,%3};"
        : "+f"(c[0]), "+f"(c[1]), "+f"(c[2]), "+f"(c[3])
        : "r"(a[0]), "r"(a[1]), "r"(a[2]), "r"(a[3]), "r"(b0), "r"(b1));
}

#define CPA16(s, g)  asm volatile("cp.async.cg.shared.global [%0], [%1], 16;" :: "r"(s), "l"(g))
#define CPA_COMMIT() asm volatile("cp.async.commit_group;" ::: "memory")
#define CPA_WAITN(n) asm volatile("cp.async.wait_group %0;" :: "n"(n) : "memory")

// ---------------------------------------------------------------------------
// conv_all: merged conv_x (blocks 0..6143) + conv_w (blocks 6144..6719)
// ---------------------------------------------------------------------------
__global__ __launch_bounds__(256) void conv_all(const float* __restrict__ x,
                                                const float* __restrict__ wq,
                                                const float* __restrict__ wp) {
    const int bb = blockIdx.x;
    if (bb < 6144) {
        __shared__ float t[32][33];
        const int tx = threadIdx.x & 31, ty = threadIdx.x >> 5;
        const int s0 = (bb & 127) * 32;
        const int k0 = ((bb >> 7) % 6) * 32;
        const int b  = bb / 768;
        const float* xb = x + ((size_t)b * DIM + k0) * 4096 + s0;
        #pragma unroll
        for (int r = 0; r < 4; r++)
            t[ty + 8 * r][tx] = xb[(size_t)(ty + 8 * r) * 4096 + tx];
        __syncthreads();
        #pragma unroll
        for (int r = 0; r < 4; r++) {
            const int sl = ty + 8 * r;
            const float v = t[tx][sl];
            const __nv_bfloat16 h = __float2bfloat16(v);
            const __nv_bfloat16 l = __float2bfloat16(v - __bfloat162float(h));
            __nv_bfloat16* row = g_xe + (size_t)((b << 12) + s0 + sl) * KEXT;
            row[k0 + tx]       = h;
            row[192 + k0 + tx] = l;
        }
    } else {
        int i = (bb - 6144) * 256 + threadIdx.x;
        if (i < QKVN * DIM) {
            const int n = i / DIM, k = i % DIM;
            const float v = wq[i];
            const __nv_bfloat16 h = __float2bfloat16(v);
            const __nv_bfloat16 l = __float2bfloat16(v - __bfloat162float(h));
            g_wqe[(size_t)n * KEXT + k] = h;
            g_wqe[(size_t)n * KEXT + 192 + k] = l;
        } else {
            i -= QKVN * DIM;
            if (i < DIM * DIM) {
                const int n = i / DIM, k = i % DIM;
                const float v = wp[i];
                const __nv_bfloat16 h = __float2bfloat16(v);
                const __nv_bfloat16 l = __float2bfloat16(v - __bfloat162float(h));
                g_wpe[(size_t)n * KEXT + k] = h;
                g_wpe[(size_t)n * KEXT + 192 + k] = l;
            }
        }
    }
}

// ---------------------------------------------------------------------------
// HMMA GEMM, CTA 128x64, 8 warps (4m x 2n), extended-K split.
// B resident (48 KB); A streamed in 6 octs of 16 KB via 4-slot ring (64 KB).
// Grid: x = n-tile (few), y = m-block (many) -> consecutive CTAs share A in L2.
// EPI=0: routed q/k/v stores.  EPI=1: CHW out.
// ---------------------------------------------------------------------------
#define MT 128
#define NT 64
#define SM_B 0                      // B: 64 rows x 768 B = 49152
#define SM_A 49152                  // A ring: 4 x 16384
#define SM_TOT 114688

template<int EPI>
__global__ __launch_bounds__(256, 2) void hmma_gemm(const __nv_bfloat16* __restrict__ A,
                                                    const __nv_bfloat16* __restrict__ Bw,
                                                    const float* __restrict__ bias,
                                                    float* __restrict__ outp) {
    extern __shared__ char smem[];
    const u32 sb = sToU32(smem);
    const int tid = threadIdx.x;
    const int wid = tid >> 5, lane = tid & 31;
    const int m0 = blockIdx.y * MT;          // m on y (slow-varying)
    const int n0 = blockIdx.x * NT;          // n on x (fast-varying)

    const __nv_bfloat16* Ab = A + (size_t)m0 * KEXT;
    const __nv_bfloat16* Bb = Bw + (size_t)n0 * KEXT;

    // ---- prologue: B (48 KB, group0) then A octs 0..3 (16 KB each, groups 1-4)
    #pragma unroll
    for (int i = 0; i < 12; i++) {                       // B: 64 rows x 48 chunks
        const int idx = tid + i * 256;
        const int r = idx / 48, c = idx % 48;
        CPA16(sb + SM_B + r * 768 + ((c ^ (r & 7)) << 4), Bb + (size_t)r * KEXT + c * 8);
    }
    CPA_COMMIT();
    #pragma unroll
    for (int o = 0; o < 4; o++) {                        // A octs: 128 rows x 8 chunks
        #pragma unroll
        for (int i = 0; i < 4; i++) {
            const int idx = tid + i * 256;
            const int r = idx >> 3, c = idx & 7;
            CPA16(sb + SM_A + o * 16384 + r * 128 + ((c ^ (r & 7)) << 4),
                  Ab + (size_t)r * KEXT + (o * 8 + c) * 8);
        }
        CPA_COMMIT();
    }

    const int warpM = (wid >> 1) * 32;
    const int warpN = (wid & 1) * 32;
    const int lr = lane & 15;
    const int lh = lane >> 4;
    const int asw = lr & 7;
    u32 bBase[2]; int bsw[2];
    #pragma unroll
    for (int g = 0; g < 2; g++) {
        const int row = warpN + g * 16 + lr;
        bBase[g] = sb + SM_B + row * 768;
        bsw[g]   = row & 7;
    }

    float acc[2][4][4] = {};

    #pragma unroll
    for (int st = 0; st < 6; st++) {
        if (st < 3) { CPA_WAITN(3); }
        else if (st == 3) { CPA_WAITN(2); }
        else if (st == 4) { CPA_WAITN(1); }
        else { CPA_WAITN(0); }
        __syncthreads();

        const int slot = st & 3;
        const u32 aB = sb + SM_A + slot * 16384 + (warpM + lr) * 128;
        const int nk = (st < 3) ? 8 : 4;
        #pragma unroll
        for (int kk = 0; kk < 8; kk++) {
            if (kk >= nk) break;
            const int boct = (st < 3) ? ((kk < 4) ? st : st + 3) : (st - 3);
            const int al = kk & 3;
            u32 af0[4], af1[4];
            LDSM4(af0, aB + (((al * 2 + lh) ^ asw) << 4));
            LDSM4(af1, aB + 16 * 128 + (((al * 2 + lh) ^ asw) << 4));
            const int bc = boct * 8 + al * 2 + lh;
            u32 bf[2][4];
            #pragma unroll
            for (int g = 0; g < 2; g++)
                LDSM4(bf[g], bBase[g] + ((bc ^ bsw[g]) << 4));
            #pragma unroll
            for (int j = 0; j < 4; j++) {
                const int g = j >> 1, p = j & 1;
                hmma(acc[0][j], af0, bf[g][p], bf[g][p + 2]);
                hmma(acc[1][j], af1, bf[g][p], bf[g][p + 2]);
            }
        }
        __syncthreads();
        if (st < 2) {
            #pragma unroll
            for (int i = 0; i < 4; i++) {
                const int idx = tid + i * 256;
                const int r = idx >> 3, c = idx & 7;
                CPA16(sb + SM_A + slot * 16384 + r * 128 + ((c ^ (r & 7)) << 4),
                      Ab + (size_t)r * KEXT + ((st + 4) * 8 + c) * 8);
            }
            CPA_COMMIT();
        }
    }

    // ---- epilogue (smem reuse)
    if (EPI == 0) {
        float* Ct = (float*)smem;   // [128][68]
        #pragma unroll
        for (int mt = 0; mt < 2; mt++) {
            #pragma unroll
            for (int j = 0; j < 4; j++) {
                const int rm = warpM + mt * 16 + (lane >> 2);
                const int rn = warpN + j * 8 + (lane & 3) * 2;
                Ct[rm * 68 + rn]           = acc[mt][j][0];
                Ct[rm * 68 + rn + 1]       = acc[mt][j][1];
                Ct[(rm + 8) * 68 + rn]     = acc[mt][j][2];
                Ct[(rm + 8) * 68 + rn + 1] = acc[mt][j][3];
            }
        }
        __syncthreads();
        // whole 64-wide tile maps to one section: q (sec 0), k (1), or v (2)
        const int br = n0 / 192, rr = n0 % 192, sec = rr >> 6;
        #pragma unroll
        for (int i = 0; i < 8; i++) {
            const int idx = tid + i * 256;          // 2048 stores
            const int m = idx >> 4, c = (idx & 15) * 4;
            const float4 bv = *(const float4*)&bias[n0 + c];
            float4 v;
            v.x = Ct[m * 68 + c]     + bv.x;
            v.y = Ct[m * 68 + c + 1] + bv.y;
            v.z = Ct[m * 68 + c + 2] + bv.z;
            v.w = Ct[m * 68 + c + 3] + bv.w;
            const size_t pix = m0 + m;
            if (sec == 0) {
                const float qsc = 0.17677669529663687f;
                v.x *= qsc; v.y *= qsc; v.z *= qsc; v.w *= qsc;
                *(float4*)&g_q[pix * DIM + br * 64 + c] = v;
            } else {
                __half2 h0 = __float22half2_rn(make_float2(v.x, v.y));
                __half2 h1 = __float22half2_rn(make_float2(v.z, v.w));
                __half* dst = (sec == 1) ? g_k : g_v;
                __half2* vp = (__half2*)&dst[((size_t)(br << 15) + pix) * 64 + c];
                vp[0] = h0; vp[1] = h1;
            }
        }
    } else {
        float* Ct = (float*)smem;   // [64][132] transposed
        #pragma unroll
        for (int mt = 0; mt < 2; mt++) {
            #pragma unroll
            for (int j = 0; j < 4; j++) {
                const int rn = warpN + j * 8 + (lane & 3) * 2;
                const int rm = warpM + mt * 16 + (lane >> 2);
                Ct[rn * 132 + rm]           = acc[mt][j][0];
                Ct[(rn + 1) * 132 + rm]     = acc[mt][j][1];
                Ct[rn * 132 + rm + 8]       = acc[mt][j][2];
                Ct[(rn + 1) * 132 + rm + 8] = acc[mt][j][3];
            }
        }
        __syncthreads();
        const int b = m0 >> 12, s0 = m0 & 4095;
        float* ob = outp + ((size_t)b * DIM + n0) * 4096 + s0;
        #pragma unroll
        for (int i = 0; i < 32; i++) {
            const int idx = tid + i * 256;
            const int n = idx >> 7, m = idx & 127;
            ob[(size_t)n * 4096 + m] = Ct[n * 132 + m] + bias[n0 + n];
        }
    }
}

// ---------------------------------------------------------------------------
// NATTEN: 8 lanes per (pixel, head); k,v fp16 (fp32 math); rpb in smem;
// k+v rows loaded together; max-free softmax. Output split bf16 into g_ye.
// ---------------------------------------------------------------------------
template<int K, int D, int BR>
__device__ __forceinline__ void natten_body(const float* __restrict__ rpb, int blk,
                                            float* __restrict__ srpb) {
    for (int i = threadIdx.x; i < 2 * (2 * K - 1) * (2 * K - 1); i += 256)
        srpb[i] = rpb[i];
    __syncthreads();

    const int sl   = threadIdx.x & 7;
    const int gid  = (blk * 256 + threadIdx.x) >> 3;
    const int head = gid & 1;
    const int pix  = gid >> 1;
    const int w = pix & 63;
    const int h = (pix >> 6) & 63;
    const int b = pix >> 12;

    const float4 q = *(const float4*)&g_q[(size_t)pix * DIM + BR * 64 + head * HEADD + sl * 4];

    const int gh = h % D, iih = h / D;
    const int Lgh = (HH - gh + D - 1) / D;
    const int sth = min(max(iih - K / 2, 0), Lgh - K);
    const int gw = w % D, iiw = w / D;
    const int Lgw = (WW - gw + D - 1) / D;
    const int stw = min(max(iiw - K / 2, 0), Lgw - K);

    const float* rpbh = srpb + head * (2 * K - 1) * (2 * K - 1)
                       + (sth - iih + K - 1) * (2 * K - 1)
                       + (stw - iiw + K - 1);

    const size_t nb0 = (size_t)(BR << 15) + (b << 12) + (gh + sth * D) * 64 + (gw + stw * D);
    const __half* kbase = g_k + nb0 * 64 + head * HEADD + sl * 4;
    const __half* vbase = g_v + nb0 * 64 + head * HEADD + sl * 4;

    const int strideWk = D * 64;
    const int strideHk = D * 64 * 64;

    float l = 0.f;
    u64 acc0 = 0, acc1 = 0;

    #pragma unroll
    for (int kh = 0; kh < K; kh++) {
        const __half* pk = kbase + (size_t)kh * strideHk;
        const __half* pv = vbase + (size_t)kh * strideHk;
        float sarr[K];
        u64 varr[K];
        #pragma unroll
        for (int kw = 0; kw < K; kw++) {
            const u64 k4p = *(const u64*)(pk + (size_t)kw * strideWk);
            varr[kw] = *(const u64*)(pv + (size_t)kw * strideWk);
            const __half2* kh2 = (const __half2*)&k4p;
            const float2 k01 = __half22float2(kh2[0]);
            const float2 k23 = __half22float2(kh2[1]);
            sarr[kw] = q.x * k01.x + q.y * k01.y + q.z * k23.x + q.w * k23.y;
        }
        #pragma unroll
        for (int kw = 0; kw < K; kw++) {
            float s = sarr[kw];
            s += __shfl_xor_sync(0xffffffffu, s, 4);
            s += __shfl_xor_sync(0xffffffffu, s, 2);
            s += __shfl_xor_sync(0xffffffffu, s, 1);
            sarr[kw] = __expf(s + rpbh[kh * (2 * K - 1) + kw]);
        }
        #pragma unroll
        for (int kw = 0; kw < K; kw++) {
            const float pr = sarr[kw];
            l += pr;
            const u64 prd = dup2(pr);
            const __half2* vh = (const __half2*)&varr[kw];
            const float2 f01 = __half22float2(vh[0]);
            const float2 f23 = __half22float2(vh[1]);
            ffma2(acc0, pk2(f01.x, f01.y), prd);
            ffma2(acc1, pk2(f23.x, f23.y), prd);
        }
    }
    const float rinv = __frcp_rn(l);
    float o[4];
    unpk2(acc0, o[0], o[1]);
    unpk2(acc1, o[2], o[3]);

    const int c = BR * 64 + head * HEADD + sl * 4;
    __nv_bfloat16 hi[4], lo[4];
    #pragma unroll
    for (int i = 0; i < 4; i++) {
        const float v = o[i] * rinv;
        hi[i] = __float2bfloat16(v);
        lo[i] = __float2bfloat16(v - __bfloat162float(hi[i]));
    }
    __nv_bfloat16* yr = g_ye + (size_t)pix * KEXT;
    *(u64*)(yr + c)       = *(const u64*)hi;
    *(u64*)(yr + 192 + c) = *(const u64*)lo;
}

#define ABLOCKS (NPIX * HEADSB / 32)   // 2048 blocks per branch

__global__ __launch_bounds__(256) void natten_all(const float* __restrict__ rpb0,
                                                  const float* __restrict__ rpb1,
                                                  const float* __restrict__ rpb2) {
    __shared__ float srpb[338];
    const int br  = blockIdx.x % 3;
    const int idx = blockIdx.x / 3;
    if (br == 0)      natten_body<3, 1, 0>(rpb0, idx, srpb);
    else if (br == 1) natten_body<5, 2, 1>(rpb1, idx, srpb);
    else              natten_body<7, 3, 2>(rpb2, idx, srpb);
}

// ---------------------------------------------------------------------------
extern "C" void kernel_launch(void* const* d_in, const int* in_sizes, int n_in,
                              void* d_out, int out_size) {
    const float* x      = (const float*)d_in[0];
    const float* qkv_w  = (const float*)d_in[1];
    const float* qkv_b  = (const float*)d_in[2];
    const float* proj_w = (const float*)d_in[3];
    const float* proj_b = (const float*)d_in[4];
    const float* rpb0   = (const float*)d_in[5];
    const float* rpb1   = (const float*)d_in[6];
    const float* rpb2   = (const float*)d_in[7];
    float* out = (float*)d_out;

    static bool init_done = false;
    if (!init_done) {
        cudaFuncSetAttribute(hmma_gemm<0>, cudaFuncAttributeMaxDynamicSharedMemorySize, SM_TOT);
        cudaFuncSetAttribute(hmma_gemm<1>, cudaFuncAttributeMaxDynamicSharedMemorySize, SM_TOT);
        init_done = true;
    }

    __nv_bfloat16* xe  = nullptr; cudaGetSymbolAddress((void**)&xe,  g_xe);
    __nv_bfloat16* ye  = nullptr; cudaGetSymbolAddress((void**)&ye,  g_ye);
    __nv_bfloat16* wqe = nullptr; cudaGetSymbolAddress((void**)&wqe, g_wqe);
    __nv_bfloat16* wpe = nullptr; cudaGetSymbolAddress((void**)&wpe, g_wpe);

    conv_all<<<6720, 256>>>(x, qkv_w, proj_w);

    // grid: x = n-tiles (9 / 3), y = m-blocks (256) -> A stays hot in L2
    hmma_gemm<0><<<dim3(QKVN / NT, NPIX / MT), 256, SM_TOT>>>(xe, wqe, qkv_b, nullptr);

    natten_all<<<3 * ABLOCKS, 256>>>(rpb0, rpb1, rpb2);

    hmma_gemm<1><<<dim3(DIM / NT, NPIX / MT), 256, SM_TOT>>>(ye, wpe, proj_b, out);
}

// round 17
// speedup vs baseline: 1.1250x; 1.1080x over previous
#include <cuda_runtime.h>
#include <cuda_bf16.h>
#include <cuda_fp16.h>
#include <cstdint>

#define BB     8
#define HH     64
#define WW     64
#define NPIX   32768
#define DIM    192
#define QKVN   576
#define HEADSB 2
#define HEADD  32
#define KEXT   384        // hi(192) | lo(192)

typedef unsigned long long u64;
typedef unsigned int u32;

// Scratch (device globals: allocation-free rule)
__device__ float         g_q[(size_t)NPIX * DIM];          // pre-scaled q, [pix][192]
__device__ __half        g_k[(size_t)3 * NPIX * 64];       // [branch][pix][64] fp16
__device__ __half        g_v[(size_t)3 * NPIX * 64];       // [branch][pix][64] fp16
__device__ __half        g_xe[(size_t)NPIX * KEXT];        // x^T split hi|lo fp16
__device__ __half        g_wq[(size_t)QKVN * DIM];         // qkv_w single fp16
__device__ __nv_bfloat16 g_ye[(size_t)NPIX * KEXT];        // y split hi|lo bf16
__device__ __nv_bfloat16 g_wpe[(size_t)DIM * KEXT];        // proj_w split bf16

// ---- f32x2 helpers ---------------------------------------------------------
__device__ __forceinline__ void ffma2(u64& d, u64 a, u64 b) {
    asm("fma.rn.f32x2 %0, %1, %2, %0;" : "+l"(d) : "l"(a), "l"(b));
}
__device__ __forceinline__ u64 dup2(float v) {
    u64 r; asm("mov.b64 %0, {%1, %1};" : "=l"(r) : "f"(v)); return r;
}
__device__ __forceinline__ u64 pk2(float lo, float hi) {
    u64 r; asm("mov.b64 %0, {%1, %2};" : "=l"(r) : "f"(lo), "f"(hi)); return r;
}
__device__ __forceinline__ void unpk2(u64 v, float& lo, float& hi) {
    asm("mov.b64 {%0, %1}, %2;" : "=f"(lo), "=f"(hi) : "l"(v));
}
__device__ __forceinline__ u32 sToU32(const void* p) {
    u32 a;
    asm("{ .reg .u64 t; cvta.to.shared.u64 t, %1; cvt.u32.u64 %0, t; }" : "=r"(a) : "l"(p));
    return a;
}

// ---- warp MMA primitives ----------------------------------------------------
#define LDSM4(r, addr) \
    asm volatile("ldmatrix.sync.aligned.m8n8.x4.shared.b16 {%0,%1,%2,%3}, [%4];" \
                 : "=r"((r)[0]), "=r"((r)[1]), "=r"((r)[2]), "=r"((r)[3]) : "r"(addr))

__device__ __forceinline__ void hmma_bf16(float* c, const u32* a, u32 b0, u32 b1) {
    asm volatile(
        "mma.sync.aligned.m16n8k16.row.col.f32.bf16.bf16.f32 "
        "{%0,%1,%2,%3}, {%4,%5,%6,%7}, {%8,%9}, {%0,%1,%2,%3};"
        : "+f"(c[0]), "+f"(c[1]), "+f"(c[2]), "+f"(c[3])
        : "r"(a[0]), "r"(a[1]), "r"(a[2]), "r"(a[3]), "r"(b0), "r"(b1));
}
__device__ __forceinline__ void hmma_f16(float* c, const u32* a, u32 b0, u32 b1) {
    asm volatile(
        "mma.sync.aligned.m16n8k16.row.col.f32.f16.f16.f32 "
        "{%0,%1,%2,%3}, {%4,%5,%6,%7}, {%8,%9}, {%0,%1,%2,%3};"
        : "+f"(c[0]), "+f"(c[1]), "+f"(c[2]), "+f"(c[3])
        : "r"(a[0]), "r"(a[1]), "r"(a[2]), "r"(a[3]), "r"(b0), "r"(b1));
}

#define CPA16(s, g)  asm volatile("cp.async.cg.shared.global [%0], [%1], 16;" :: "r"(s), "l"(g))
#define CPA_COMMIT() asm volatile("cp.async.commit_group;" ::: "memory")
#define CPA_WAITN(n) asm volatile("cp.async.wait_group %0;" :: "n"(n) : "memory")

// ---------------------------------------------------------------------------
// conv_all: blocks 0..6143 transpose+split x (fp16 hi|lo);
//           blocks 6144..6719 split weights (wq fp16 single, wp bf16 hi|lo)
// ---------------------------------------------------------------------------
__global__ __launch_bounds__(256) void conv_all(const float* __restrict__ x,
                                                const float* __restrict__ wq,
                                                const float* __restrict__ wp) {
    const int bb = blockIdx.x;
    if (bb < 6144) {
        __shared__ float t[32][33];
        const int tx = threadIdx.x & 31, ty = threadIdx.x >> 5;
        const int s0 = (bb & 127) * 32;
        const int k0 = ((bb >> 7) % 6) * 32;
        const int b  = bb / 768;
        const float* xb = x + ((size_t)b * DIM + k0) * 4096 + s0;
        #pragma unroll
        for (int r = 0; r < 4; r++)
            t[ty + 8 * r][tx] = xb[(size_t)(ty + 8 * r) * 4096 + tx];
        __syncthreads();
        #pragma unroll
        for (int r = 0; r < 4; r++) {
            const int sl = ty + 8 * r;
            const float v = t[tx][sl];
            const __half h = __float2half(v);
            const __half l = __float2half(v - __half2float(h));
            __half* row = g_xe + (size_t)((b << 12) + s0 + sl) * KEXT;
            row[k0 + tx]       = h;
            row[192 + k0 + tx] = l;
        }
    } else {
        int i = (bb - 6144) * 256 + threadIdx.x;
        if (i < QKVN * DIM) {
            g_wq[i] = __float2half(wq[i]);
        } else {
            i -= QKVN * DIM;
            if (i < DIM * DIM) {
                const int n = i / DIM, k = i % DIM;
                const float v = wp[i];
                const __nv_bfloat16 h = __float2bfloat16(v);
                const __nv_bfloat16 l = __float2bfloat16(v - __bfloat162float(h));
                g_wpe[(size_t)n * KEXT + k] = h;
                g_wpe[(size_t)n * KEXT + 192 + k] = l;
            }
        }
    }
}

// ---------------------------------------------------------------------------
// QKV GEMM (fp16 2-term): CTA 128x64, 8 warps. A = hi|lo fp16 (KEXT=384),
// B = single fp16 (K=192, 24 KB resident). A ring 4 x 16 KB. 24 ksteps.
// Epilogue routes q (fp32, scaled) / k / v (fp16).
// ---------------------------------------------------------------------------
#define MT 128
#define NT 64
#define QSM_B 0                     // B: 64 rows x 384 B = 24576
#define QSM_A 24576                 // A ring: 4 x 16384
#define QSM_TOT 90112

__global__ __launch_bounds__(256, 2) void qkv_gemm_f16(const __half* __restrict__ A,
                                                       const __half* __restrict__ Bw,
                                                       const float* __restrict__ bias) {
    extern __shared__ char smem[];
    const u32 sb = sToU32(smem);
    const int tid = threadIdx.x;
    const int wid = tid >> 5, lane = tid & 31;
    const int m0 = blockIdx.y * MT;
    const int n0 = blockIdx.x * NT;

    const __half* Ab = A + (size_t)m0 * KEXT;
    const __half* Bb = Bw + (size_t)n0 * DIM;

    // prologue: B (24 KB, group0) then A octs 0..3 (groups 1-4)
    #pragma unroll
    for (int i = 0; i < 6; i++) {                        // B: 64 rows x 24 chunks
        const int idx = tid + i * 256;
        const int r = idx / 24, c = idx % 24;
        CPA16(sb + QSM_B + r * 384 + ((c ^ (r & 7)) << 4), Bb + (size_t)r * DIM + c * 8);
    }
    CPA_COMMIT();
    #pragma unroll
    for (int o = 0; o < 4; o++) {                        // A octs: 128 rows x 8 chunks
        #pragma unroll
        for (int i = 0; i < 4; i++) {
            const int idx = tid + i * 256;
            const int r = idx >> 3, c = idx & 7;
            CPA16(sb + QSM_A + o * 16384 + r * 128 + ((c ^ (r & 7)) << 4),
                  Ab + (size_t)r * KEXT + (o * 8 + c) * 8);
        }
        CPA_COMMIT();
    }

    const int warpM = (wid >> 1) * 32;
    const int warpN = (wid & 1) * 32;
    const int lr = lane & 15;
    const int lh = lane >> 4;
    const int asw = lr & 7;
    u32 bBase[2]; int bsw[2];
    #pragma unroll
    for (int g = 0; g < 2; g++) {
        const int row = warpN + g * 16 + lr;
        bBase[g] = sb + QSM_B + row * 384;
        bsw[g]   = row & 7;
    }

    float acc[2][4][4] = {};

    // 6 stages x 4 ksteps: A oct st (hi 0-2, lo 3-5) paired with B oct st%3
    #pragma unroll
    for (int st = 0; st < 6; st++) {
        if (st < 3) { CPA_WAITN(3); }
        else if (st == 3) { CPA_WAITN(2); }
        else if (st == 4) { CPA_WAITN(1); }
        else { CPA_WAITN(0); }
        __syncthreads();

        const int slot = st & 3;
        const u32 aB = sb + QSM_A + slot * 16384 + (warpM + lr) * 128;
        const int bo = (st % 3) * 8;
        #pragma unroll
        for (int kk = 0; kk < 4; kk++) {
            const int al = kk * 2 + lh;
            u32 af0[4], af1[4];
            LDSM4(af0, aB + ((al ^ asw) << 4));
            LDSM4(af1, aB + 16 * 128 + ((al ^ asw) << 4));
            const int bc = bo + kk * 2 + lh;
            u32 bf[2][4];
            #pragma unroll
            for (int g = 0; g < 2; g++)
                LDSM4(bf[g], bBase[g] + ((bc ^ bsw[g]) << 4));
            #pragma unroll
            for (int j = 0; j < 4; j++) {
                const int g = j >> 1, p = j & 1;
                hmma_f16(acc[0][j], af0, bf[g][p], bf[g][p + 2]);
                hmma_f16(acc[1][j], af1, bf[g][p], bf[g][p + 2]);
            }
        }
        __syncthreads();
        if (st < 2) {
            #pragma unroll
            for (int i = 0; i < 4; i++) {
                const int idx = tid + i * 256;
                const int r = idx >> 3, c = idx & 7;
                CPA16(sb + QSM_A + slot * 16384 + r * 128 + ((c ^ (r & 7)) << 4),
                      Ab + (size_t)r * KEXT + ((st + 4) * 8 + c) * 8);
            }
            CPA_COMMIT();
        }
    }

    // epilogue (smem reuse)
    float* Ct = (float*)smem;   // [128][68]
    #pragma unroll
    for (int mt = 0; mt < 2; mt++) {
        #pragma unroll
        for (int j = 0; j < 4; j++) {
            const int rm = warpM + mt * 16 + (lane >> 2);
            const int rn = warpN + j * 8 + (lane & 3) * 2;
            Ct[rm * 68 + rn]           = acc[mt][j][0];
            Ct[rm * 68 + rn + 1]       = acc[mt][j][1];
            Ct[(rm + 8) * 68 + rn]     = acc[mt][j][2];
            Ct[(rm + 8) * 68 + rn + 1] = acc[mt][j][3];
        }
    }
    __syncthreads();
    const int br = n0 / 192, rr = n0 % 192, sec = rr >> 6;
    #pragma unroll
    for (int i = 0; i < 8; i++) {
        const int idx = tid + i * 256;
        const int m = idx >> 4, c = (idx & 15) * 4;
        const float4 bv = *(const float4*)&bias[n0 + c];
        float4 v;
        v.x = Ct[m * 68 + c]     + bv.x;
        v.y = Ct[m * 68 + c + 1] + bv.y;
        v.z = Ct[m * 68 + c + 2] + bv.z;
        v.w = Ct[m * 68 + c + 3] + bv.w;
        const size_t pix = m0 + m;
        if (sec == 0) {
            const float qsc = 0.17677669529663687f;
            v.x *= qsc; v.y *= qsc; v.z *= qsc; v.w *= qsc;
            *(float4*)&g_q[pix * DIM + br * 64 + c] = v;
        } else {
            __half2 h0 = __float22half2_rn(make_float2(v.x, v.y));
            __half2 h1 = __float22half2_rn(make_float2(v.z, v.w));
            __half* dst = (sec == 1) ? g_k : g_v;
            __half2* vp = (__half2*)&dst[((size_t)(br << 15) + pix) * 64 + c];
            vp[0] = h0; vp[1] = h1;
        }
    }
}

// ---------------------------------------------------------------------------
// Proj GEMM (bf16 3-term, known-good R12 shape): CTA 128x64, B 48 KB resident,
// A ring 4 x 16 KB, 36 ksteps. CHW output.
// ---------------------------------------------------------------------------
#define SM_B 0
#define SM_A 49152
#define SM_TOT 114688

__global__ __launch_bounds__(256, 2) void proj_gemm_bf16(const __nv_bfloat16* __restrict__ A,
                                                         const __nv_bfloat16* __restrict__ Bw,
                                                         const float* __restrict__ bias,
                                                         float* __restrict__ outp) {
    extern __shared__ char smem[];
    const u32 sb = sToU32(smem);
    const int tid = threadIdx.x;
    const int wid = tid >> 5, lane = tid & 31;
    const int m0 = blockIdx.y * MT;
    const int n0 = blockIdx.x * NT;

    const __nv_bfloat16* Ab = A + (size_t)m0 * KEXT;
    const __nv_bfloat16* Bb = Bw + (size_t)n0 * KEXT;

    #pragma unroll
    for (int i = 0; i < 12; i++) {                       // B: 64 rows x 48 chunks
        const int idx = tid + i * 256;
        const int r = idx / 48, c = idx % 48;
        CPA16(sb + SM_B + r * 768 + ((c ^ (r & 7)) << 4), Bb + (size_t)r * KEXT + c * 8);
    }
    CPA_COMMIT();
    #pragma unroll
    for (int o = 0; o < 4; o++) {
        #pragma unroll
        for (int i = 0; i < 4; i++) {
            const int idx = tid + i * 256;
            const int r = idx >> 3, c = idx & 7;
            CPA16(sb + SM_A + o * 16384 + r * 128 + ((c ^ (r & 7)) << 4),
                  Ab + (size_t)r * KEXT + (o * 8 + c) * 8);
        }
        CPA_COMMIT();
    }

    const int warpM = (wid >> 1) * 32;
    const int warpN = (wid & 1) * 32;
    const int lr = lane & 15;
    const int lh = lane >> 4;
    const int asw = lr & 7;
    u32 bBase[2]; int bsw[2];
    #pragma unroll
    for (int g = 0; g < 2; g++) {
        const int row = warpN + g * 16 + lr;
        bBase[g] = sb + SM_B + row * 768;
        bsw[g]   = row & 7;
    }

    float acc[2][4][4] = {};

    #pragma unroll
    for (int st = 0; st < 6; st++) {
        if (st < 3) { CPA_WAITN(3); }
        else if (st == 3) { CPA_WAITN(2); }
        else if (st == 4) { CPA_WAITN(1); }
        else { CPA_WAITN(0); }
        __syncthreads();

        const int slot = st & 3;
        const u32 aB = sb + SM_A + slot * 16384 + (warpM + lr) * 128;
        const int nk = (st < 3) ? 8 : 4;
        #pragma unroll
        for (int kk = 0; kk < 8; kk++) {
            if (kk >= nk) break;
            const int boct = (st < 3) ? ((kk < 4) ? st : st + 3) : (st - 3);
            const int al = kk & 3;
            u32 af0[4], af1[4];
            LDSM4(af0, aB + (((al * 2 + lh) ^ asw) << 4));
            LDSM4(af1, aB + 16 * 128 + (((al * 2 + lh) ^ asw) << 4));
            const int bc = boct * 8 + al * 2 + lh;
            u32 bf[2][4];
            #pragma unroll
            for (int g = 0; g < 2; g++)
                LDSM4(bf[g], bBase[g] + ((bc ^ bsw[g]) << 4));
            #pragma unroll
            for (int j = 0; j < 4; j++) {
                const int g = j >> 1, p = j & 1;
                hmma_bf16(acc[0][j], af0, bf[g][p], bf[g][p + 2]);
                hmma_bf16(acc[1][j], af1, bf[g][p], bf[g][p + 2]);
            }
        }
        __syncthreads();
        if (st < 2) {
            #pragma unroll
            for (int i = 0; i < 4; i++) {
                const int idx = tid + i * 256;
                const int r = idx >> 3, c = idx & 7;
                CPA16(sb + SM_A + slot * 16384 + r * 128 + ((c ^ (r & 7)) << 4),
                      Ab + (size_t)r * KEXT + ((st + 4) * 8 + c) * 8);
            }
            CPA_COMMIT();
        }
    }

    float* Ct = (float*)smem;   // [64][132] transposed
    #pragma unroll
    for (int mt = 0; mt < 2; mt++) {
        #pragma unroll
        for (int j = 0; j < 4; j++) {
            const int rn = warpN + j * 8 + (lane & 3) * 2;
            const int rm = warpM + mt * 16 + (lane >> 2);
            Ct[rn * 132 + rm]           = acc[mt][j][0];
            Ct[(rn + 1) * 132 + rm]     = acc[mt][j][1];
            Ct[rn * 132 + rm + 8]       = acc[mt][j][2];
            Ct[(rn + 1) * 132 + rm + 8] = acc[mt][j][3];
        }
    }
    __syncthreads();
    const int b = m0 >> 12, s0 = m0 & 4095;
    float* ob = outp + ((size_t)b * DIM + n0) * 4096 + s0;
    #pragma unroll
    for (int i = 0; i < 32; i++) {
        const int idx = tid + i * 256;
        const int n = idx >> 7, m = idx & 127;
        ob[(size_t)n * 4096 + m] = Ct[n * 132 + m] + bias[n0 + n];
    }
}

// ---------------------------------------------------------------------------
// NATTEN: 8 lanes per (pixel, head); k,v fp16 (fp32 math); rpb in smem;
// k+v rows loaded together; max-free softmax. Output split bf16 into g_ye.
// ---------------------------------------------------------------------------
template<int K, int D, int BR>
__device__ __forceinline__ void natten_body(const float* __restrict__ rpb, int blk,
                                            float* __restrict__ srpb) {
    for (int i = threadIdx.x; i < 2 * (2 * K - 1) * (2 * K - 1); i += 256)
        srpb[i] = rpb[i];
    __syncthreads();

    const int sl   = threadIdx.x & 7;
    const int gid  = (blk * 256 + threadIdx.x) >> 3;
    const int head = gid & 1;
    const int pix  = gid >> 1;
    const int w = pix & 63;
    const int h = (pix >> 6) & 63;
    const int b = pix >> 12;

    const float4 q = *(const float4*)&g_q[(size_t)pix * DIM + BR * 64 + head * HEADD + sl * 4];

    const int gh = h % D, iih = h / D;
    const int Lgh = (HH - gh + D - 1) / D;
    const int sth = min(max(iih - K / 2, 0), Lgh - K);
    const int gw = w % D, iiw = w / D;
    const int Lgw = (WW - gw + D - 1) / D;
    const int stw = min(max(iiw - K / 2, 0), Lgw - K);

    const float* rpbh = srpb + head * (2 * K - 1) * (2 * K - 1)
                       + (sth - iih + K - 1) * (2 * K - 1)
                       + (stw - iiw + K - 1);

    const size_t nb0 = (size_t)(BR << 15) + (b << 12) + (gh + sth * D) * 64 + (gw + stw * D);
    const __half* kbase = g_k + nb0 * 64 + head * HEADD + sl * 4;
    const __half* vbase = g_v + nb0 * 64 + head * HEADD + sl * 4;

    const int strideWk = D * 64;
    const int strideHk = D * 64 * 64;

    float l = 0.f;
    u64 acc0 = 0, acc1 = 0;

    #pragma unroll
    for (int kh = 0; kh < K; kh++) {
        const __half* pk = kbase + (size_t)kh * strideHk;
        const __half* pv = vbase + (size_t)kh * strideHk;
        float sarr[K];
        u64 varr[K];
        #pragma unroll
        for (int kw = 0; kw < K; kw++) {
            const u64 k4p = *(const u64*)(pk + (size_t)kw * strideWk);
            varr[kw] = *(const u64*)(pv + (size_t)kw * strideWk);
            const __half2* kh2 = (const __half2*)&k4p;
            const float2 k01 = __half22float2(kh2[0]);
            const float2 k23 = __half22float2(kh2[1]);
            sarr[kw] = q.x * k01.x + q.y * k01.y + q.z * k23.x + q.w * k23.y;
        }
        #pragma unroll
        for (int kw = 0; kw < K; kw++) {
            float s = sarr[kw];
            s += __shfl_xor_sync(0xffffffffu, s, 4);
            s += __shfl_xor_sync(0xffffffffu, s, 2);
            s += __shfl_xor_sync(0xffffffffu, s, 1);
            sarr[kw] = __expf(s + rpbh[kh * (2 * K - 1) + kw]);
        }
        #pragma unroll
        for (int kw = 0; kw < K; kw++) {
            const float pr = sarr[kw];
            l += pr;
            const u64 prd = dup2(pr);
            const __half2* vh = (const __half2*)&varr[kw];
            const float2 f01 = __half22float2(vh[0]);
            const float2 f23 = __half22float2(vh[1]);
            ffma2(acc0, pk2(f01.x, f01.y), prd);
            ffma2(acc1, pk2(f23.x, f23.y), prd);
        }
    }
    const float rinv = __frcp_rn(l);
    float o[4];
    unpk2(acc0, o[0], o[1]);
    unpk2(acc1, o[2], o[3]);

    const int c = BR * 64 + head * HEADD + sl * 4;
    __nv_bfloat16 hi[4], lo[4];
    #pragma unroll
    for (int i = 0; i < 4; i++) {
        const float v = o[i] * rinv;
        hi[i] = __float2bfloat16(v);
        lo[i] = __float2bfloat16(v - __bfloat162float(hi[i]));
    }
    __nv_bfloat16* yr = g_ye + (size_t)pix * KEXT;
    *(u64*)(yr + c)       = *(const u64*)hi;
    *(u64*)(yr + 192 + c) = *(const u64*)lo;
}

#define ABLOCKS (NPIX * HEADSB / 32)   // 2048 blocks per branch

__global__ __launch_bounds__(256) void natten_all(const float* __restrict__ rpb0,
                                                  const float* __restrict__ rpb1,
                                                  const float* __restrict__ rpb2) {
    __shared__ float srpb[338];
    const int br  = blockIdx.x % 3;
    const int idx = blockIdx.x / 3;
    if (br == 0)      natten_body<3, 1, 0>(rpb0, idx, srpb);
    else if (br == 1) natten_body<5, 2, 1>(rpb1, idx, srpb);
    else              natten_body<7, 3, 2>(rpb2, idx, srpb);
}

// ---------------------------------------------------------------------------
extern "C" void kernel_launch(void* const* d_in, const int* in_sizes, int n_in,
                              void* d_out, int out_size) {
    const float* x      = (const float*)d_in[0];
    const float* qkv_w  = (const float*)d_in[1];
    const float* qkv_b  = (const float*)d_in[2];
    const float* proj_w = (const float*)d_in[3];
    const float* proj_b = (const float*)d_in[4];
    const float* rpb0   = (const float*)d_in[5];
    const float* rpb1   = (const float*)d_in[6];
    const float* rpb2   = (const float*)d_in[7];
    float* out = (float*)d_out;

    static bool init_done = false;
    if (!init_done) {
        cudaFuncSetAttribute(qkv_gemm_f16, cudaFuncAttributeMaxDynamicSharedMemorySize, QSM_TOT);
        cudaFuncSetAttribute(proj_gemm_bf16, cudaFuncAttributeMaxDynamicSharedMemorySize, SM_TOT);
        init_done = true;
    }

    __half*        xe  = nullptr; cudaGetSymbolAddress((void**)&xe,  g_xe);
    __half*        wq  = nullptr; cudaGetSymbolAddress((void**)&wq,  g_wq);
    __nv_bfloat16* ye  = nullptr; cudaGetSymbolAddress((void**)&ye,  g_ye);
    __nv_bfloat16* wpe = nullptr; cudaGetSymbolAddress((void**)&wpe, g_wpe);

    conv_all<<<6720, 256>>>(x, qkv_w, proj_w);

    qkv_gemm_f16<<<dim3(QKVN / NT, NPIX / MT), 256, QSM_TOT>>>(xe, wq, qkv_b);

    natten_all<<<3 * ABLOCKS, 256>>>(rpb0, rpb1, rpb2);

    proj_gemm_bf16<<<dim3(DIM / NT, NPIX / MT), 256, SM_TOT>>>(ye, wpe, proj_b, out);
}